// round 11
// baseline (speedup 1.0000x reference)
#include <cuda_runtime.h>
#include <math.h>
#include <stdint.h>

#define EPSV 1e-5f

// ---------------- scratch (static device globals; no allocs) ----------------
__device__ float g_h1[4 * 64 * 64 * 128];    // conv1 out, NHWC (tf32-rounded)
__device__ float g_h2[16384 * 256];          // conv2 out, NHWC (tf32-rounded)
__device__ float g_s[4096 * 256];            // sequence [b*l, dm] (full fp32)
__device__ float g_sr[4096 * 256];           // tf32-rounded mirror of g_s
__device__ float g_xr[4096 * 1024];          // in_proj out, xi half (cols 0..511)
__device__ float g_xlt[512 * 4096];          // depthwise conv out, TRANSPOSED [d][row]
__device__ float g_xdbl[4096 * 64];          // x_proj out (dt|B|C)
__device__ float g_rest[512 * 4096];         // silu(res), TRANSPOSED [d][row]
__device__ float g_yt[512 * 4096];           // scan out, TRANSPOSED [d][row], tf32-rounded
__device__ float g_tmp[4096 * 256];          // out_proj out
__device__ float g_part[128 * 256];          // head partials
__device__ float g_v[4 * 256];               // pooled+LN features
__device__ float g_w2p[256 * 1152];          // permuted conv2 weights (tf32-rounded)
__device__ float g_wpp[256 * 1024];          // permuted patchify weights (tf32-rounded)
__device__ float g_ipwr[4 * 1024 * 256];     // rounded in_proj weights
__device__ float g_opwr[4 * 256 * 512];      // rounded out_proj weights

__device__ __forceinline__ float gelu_f(float v) {
    return 0.5f * v * (1.f + erff(v * 0.70710678118654752440f));
}
__device__ __forceinline__ float softplus_f(float x) {
    return fmaxf(x, 0.f) + log1pf(expf(-fabsf(x)));
}
__device__ __forceinline__ uint32_t cvt_tf32(float f) {
    uint32_t r;
    asm("cvt.rna.tf32.f32 %0, %1;" : "=r"(r) : "f"(f));
    return r;
}
__device__ __forceinline__ float tf32r(float f) {
    return __uint_as_float(cvt_tf32(f));
}

// ---------------- A-tile source: 0=plain, 1=conv3x3 on g_h1, 2=patchify g_h2 -
template <int AMODE>
__device__ __forceinline__ void srcA(const float* __restrict__ A, int lda,
                                     int gr, int gk, const float*& p, int& sz) {
    if (AMODE == 0) {
        p = A + (size_t)gr * lda + gk;
        sz = 16;
    } else if (AMODE == 1) {
        int b = gr >> 12, yy = (gr >> 6) & 63, xx = gr & 63;
        int r = gk >> 7, ci = gk & 127;
        int ky = r / 3, kx = r - ky * 3;
        int iy = yy + ky - 1, ix = xx + kx - 1;
        if ((unsigned)iy < 64u && (unsigned)ix < 64u) {
            p = &g_h1[(((b * 64 + iy) * 64 + ix) << 7) + ci];
            sz = 16;
        } else {
            p = g_h1;
            sz = 0;
        }
    } else {
        int b = gr >> 10, oy = (gr >> 5) & 31, ox = gr & 31;
        int r = gk >> 8, ci = gk & 255;
        int ky = r >> 1, kx = r & 1;
        p = &g_h2[(((b * 64 + 2 * oy + ky) * 64 + 2 * ox + kx) << 8) + ci];
        sz = 16;
    }
}

__device__ __forceinline__ void cpasync16(uint32_t dst, const void* src, int srcsz) {
    asm volatile("cp.async.cg.shared.global [%0], [%1], 16, %2;"
                 :: "r"(dst), "l"(src), "r"(srcsz));
}

template <int EPI>
__device__ __forceinline__ float epi_apply(float v, int c,
                                           const float* __restrict__ bias,
                                           const float* __restrict__ bn_g,
                                           const float* __restrict__ bn_b) {
    if (EPI == 1) v += bias[c];
    else if (EPI == 2) {
        v += bias[c];
        v = v * (bn_g[c] * rsqrtf(1.f + EPSV)) + bn_b[c];
        v = gelu_f(v);
    } else if (EPI == 4) {
        v += bias[c];
        if (c >= 512) v = v * __frcp_rn(1.f + __expf(-v));
    }
    return v;
}

#define MMA_TF32(acc, ua, ub)                                              \
    asm volatile(                                                          \
        "mma.sync.aligned.m16n8k8.row.col.f32.tf32.tf32.f32 "              \
        "{%0,%1,%2,%3}, {%4,%5,%6,%7}, {%8,%9}, {%0,%1,%2,%3};"            \
        : "+f"((acc)[0]), "+f"((acc)[1]), "+f"((acc)[2]), "+f"((acc)[3])   \
        : "r"((ua)[0]), "r"((ua)[1]), "r"((ua)[2]), "r"((ua)[3]),          \
          "r"((ub)[0]), "r"((ub)[1]))

// =========== tf32 mma.sync GEMM (NT): C[M,N] = A[M,K] * B[N,K]^T ============
// WMODE: 0=plain C write (with OUTR), 1=C + tf32-rounded mirror into Caux,
//        2=split: c<512 -> C row-major, c>=512 -> Caux[(c-512)*aux_ld + r]
template <int BM, int AMODE, int EPI, int CVTA, int OUTR, int WMODE>
__global__ void __launch_bounds__(256)
mm_gemm(const float* __restrict__ A, int lda,
        const float* __restrict__ B, int ldb,
        float* __restrict__ C, int ldc, int K,
        const float* __restrict__ bias,
        const float* __restrict__ bn_g, const float* __restrict__ bn_b,
        float* __restrict__ Caux, int aux_ld) {
    constexpr int WARPS_M = BM / 32;
    constexpr int WARPS_N = 8 / WARPS_M;
    constexpr int WN = 128 / WARPS_N;
    constexpr int NT = WN / 8;
    constexpr int AITER = BM / 32;

    extern __shared__ float sm[];
    const uint32_t sbase = (uint32_t)__cvta_generic_to_shared(sm);
    const int tid = threadIdx.x;
    const int warp = tid >> 5, lane = tid & 31;
    const int g = lane >> 2, tig = lane & 3;
    const int warpM = warp % WARPS_M, warpN = warp / WARPS_M;
    const int wm0 = warpM * 32, wn0 = warpN * WN;
    const int rowBase = blockIdx.y * BM, colBase = blockIdx.x * 128;

    float cacc[2][NT][4];
#pragma unroll
    for (int mt = 0; mt < 2; mt++)
#pragma unroll
        for (int nt = 0; nt < NT; nt++)
#pragma unroll
            for (int q = 0; q < 4; q++) cacc[mt][nt][q] = 0.f;

    const int nch = K >> 5;

    auto load_chunk = [&](int ch, int buf) {
        const int k0 = ch << 5;
        const uint32_t aBase = sbase + buf * (BM * 144);
        const uint32_t bBase = sbase + 2 * (BM * 144) + buf * 18432;
#pragma unroll
        for (int i = 0; i < AITER; i++) {
            int u = tid + i * 256;
            int row = u >> 3, c16 = u & 7;
            const float* p;
            int sz;
            srcA<AMODE>(A, lda, rowBase + row, k0 + c16 * 4, p, sz);
            cpasync16(aBase + row * 144 + c16 * 16, p, sz);
        }
#pragma unroll
        for (int i = 0; i < 4; i++) {
            int u = tid + i * 256;
            int row = u >> 3, c16 = u & 7;
            const float* p = B + (size_t)(colBase + row) * ldb + k0 + c16 * 4;
            cpasync16(bBase + row * 144 + c16 * 16, p, 16);
        }
        asm volatile("cp.async.commit_group;");
    };

    load_chunk(0, 0);
    for (int ch = 0; ch < nch; ch++) {
        const int buf = ch & 1;
        if (ch + 1 < nch) {
            load_chunk(ch + 1, buf ^ 1);
            asm volatile("cp.async.wait_group 1;" ::: "memory");
        } else {
            asm volatile("cp.async.wait_group 0;" ::: "memory");
        }
        __syncthreads();

        const float* asb = sm + buf * (BM * 36);
        const float* bsb = sm + 2 * (BM * 36) + buf * 4608;
#pragma unroll
        for (int ks = 0; ks < 4; ks++) {
            uint32_t ua[2][4];
#pragma unroll
            for (int mt = 0; mt < 2; mt++) {
                const float* Ab = asb + (wm0 + mt * 16 + g) * 36 + ks * 8 + tig;
                if (CVTA) {
                    ua[mt][0] = cvt_tf32(Ab[0]);
                    ua[mt][1] = cvt_tf32(Ab[288]);
                    ua[mt][2] = cvt_tf32(Ab[4]);
                    ua[mt][3] = cvt_tf32(Ab[292]);
                } else {
                    ua[mt][0] = __float_as_uint(Ab[0]);
                    ua[mt][1] = __float_as_uint(Ab[288]);
                    ua[mt][2] = __float_as_uint(Ab[4]);
                    ua[mt][3] = __float_as_uint(Ab[292]);
                }
            }
            uint32_t ub[NT][2];
#pragma unroll
            for (int nt = 0; nt < NT; nt++) {
                const float* Bb = bsb + (wn0 + nt * 8 + g) * 36 + ks * 8 + tig;
                ub[nt][0] = __float_as_uint(Bb[0]);
                ub[nt][1] = __float_as_uint(Bb[4]);
            }
#pragma unroll
            for (int mt = 0; mt < 2; mt++)
#pragma unroll
                for (int nt = 0; nt < NT; nt++) MMA_TF32(cacc[mt][nt], ua[mt], ub[nt]);
        }
        __syncthreads();
    }

#pragma unroll
    for (int mt = 0; mt < 2; mt++) {
        const int r0 = rowBase + wm0 + mt * 16 + g;
#pragma unroll
        for (int nt = 0; nt < NT; nt++) {
            const int cb = colBase + wn0 + nt * 8 + 2 * tig;
            float v0 = epi_apply<EPI>(cacc[mt][nt][0], cb, bias, bn_g, bn_b);
            float v1 = epi_apply<EPI>(cacc[mt][nt][1], cb + 1, bias, bn_g, bn_b);
            float v2 = epi_apply<EPI>(cacc[mt][nt][2], cb, bias, bn_g, bn_b);
            float v3 = epi_apply<EPI>(cacc[mt][nt][3], cb + 1, bias, bn_g, bn_b);
            if (WMODE == 0) {
                if (OUTR) {
                    v0 = tf32r(v0); v1 = tf32r(v1); v2 = tf32r(v2); v3 = tf32r(v3);
                }
                *(float2*)&C[(size_t)r0 * ldc + cb] = make_float2(v0, v1);
                *(float2*)&C[(size_t)(r0 + 8) * ldc + cb] = make_float2(v2, v3);
            } else if (WMODE == 1) {
                *(float2*)&C[(size_t)r0 * ldc + cb] = make_float2(v0, v1);
                *(float2*)&C[(size_t)(r0 + 8) * ldc + cb] = make_float2(v2, v3);
                *(float2*)&Caux[(size_t)r0 * ldc + cb] = make_float2(tf32r(v0), tf32r(v1));
                *(float2*)&Caux[(size_t)(r0 + 8) * ldc + cb] = make_float2(tf32r(v2), tf32r(v3));
            } else {
                if (cb < 512) {
                    *(float2*)&C[(size_t)r0 * ldc + cb] = make_float2(v0, v1);
                    *(float2*)&C[(size_t)(r0 + 8) * ldc + cb] = make_float2(v2, v3);
                } else {
                    const int d0 = cb - 512;
                    Caux[(size_t)d0 * aux_ld + r0] = v0;
                    Caux[(size_t)(d0 + 1) * aux_ld + r0] = v1;
                    Caux[(size_t)d0 * aux_ld + r0 + 8] = v2;
                    Caux[(size_t)(d0 + 1) * aux_ld + r0 + 8] = v3;
                }
            }
        }
    }
}

// =========== tf32 mma.sync GEMM (TN): C[M,N] = At^T * B^T ===================
template <int BM, int EPI>
__global__ void __launch_bounds__(256)
mm_gemm_tn(const float* __restrict__ At, int Mtot,
           const float* __restrict__ B, int ldb,
           float* __restrict__ C, int ldc, int K,
           const float* __restrict__ bias) {
    constexpr int WARPS_M = BM / 32;
    constexpr int WARPS_N = 8 / WARPS_M;
    constexpr int WN = 128 / WARPS_N;
    constexpr int NT = WN / 8;
    constexpr int AST = BM + 8;
    constexpr int ABUF = 32 * AST * 4;
    constexpr int AUNITS = (32 * BM) / 4;
    constexpr int AITER = AUNITS / 256;
    constexpr int UPR = BM / 4;

    extern __shared__ float sm[];
    const uint32_t sbase = (uint32_t)__cvta_generic_to_shared(sm);
    const int tid = threadIdx.x;
    const int warp = tid >> 5, lane = tid & 31;
    const int g = lane >> 2, tig = lane & 3;
    const int warpM = warp % WARPS_M, warpN = warp / WARPS_M;
    const int wm0 = warpM * 32, wn0 = warpN * WN;
    const int rowBase = blockIdx.y * BM, colBase = blockIdx.x * 128;

    float cacc[2][NT][4];
#pragma unroll
    for (int mt = 0; mt < 2; mt++)
#pragma unroll
        for (int nt = 0; nt < NT; nt++)
#pragma unroll
            for (int q = 0; q < 4; q++) cacc[mt][nt][q] = 0.f;

    const int nch = K >> 5;

    auto load_chunk = [&](int ch, int buf) {
        const int k0 = ch << 5;
        const uint32_t aBase = sbase + buf * ABUF;
        const uint32_t bBase = sbase + 2 * ABUF + buf * 18432;
#pragma unroll
        for (int i = 0; i < AITER; i++) {
            int u = tid + i * 256;
            int k = u / UPR, mu = u % UPR;
            const float* p = At + (size_t)(k0 + k) * Mtot + rowBase + mu * 4;
            cpasync16(aBase + k * (AST * 4) + mu * 16, p, 16);
        }
#pragma unroll
        for (int i = 0; i < 4; i++) {
            int u = tid + i * 256;
            int row = u >> 3, c16 = u & 7;
            const float* p = B + (size_t)(colBase + row) * ldb + k0 + c16 * 4;
            cpasync16(bBase + row * 144 + c16 * 16, p, 16);
        }
        asm volatile("cp.async.commit_group;");
    };

    load_chunk(0, 0);
    for (int ch = 0; ch < nch; ch++) {
        const int buf = ch & 1;
        if (ch + 1 < nch) {
            load_chunk(ch + 1, buf ^ 1);
            asm volatile("cp.async.wait_group 1;" ::: "memory");
        } else {
            asm volatile("cp.async.wait_group 0;" ::: "memory");
        }
        __syncthreads();

        const float* asb = sm + buf * (32 * AST);
        const float* bsb = sm + 2 * (32 * AST) + buf * 4608;
#pragma unroll
        for (int ks = 0; ks < 4; ks++) {
            uint32_t ua[2][4];
#pragma unroll
            for (int mt = 0; mt < 2; mt++) {
                const int m0 = wm0 + mt * 16 + g;
                const float* Ab = asb + (ks * 8 + tig) * AST + m0;
                ua[mt][0] = __float_as_uint(Ab[0]);
                ua[mt][1] = __float_as_uint(Ab[8]);
                ua[mt][2] = __float_as_uint(Ab[4 * AST]);
                ua[mt][3] = __float_as_uint(Ab[4 * AST + 8]);
            }
            uint32_t ub[NT][2];
#pragma unroll
            for (int nt = 0; nt < NT; nt++) {
                const float* Bb = bsb + (wn0 + nt * 8 + g) * 36 + ks * 8 + tig;
                ub[nt][0] = __float_as_uint(Bb[0]);
                ub[nt][1] = __float_as_uint(Bb[4]);
            }
#pragma unroll
            for (int mt = 0; mt < 2; mt++)
#pragma unroll
                for (int nt = 0; nt < NT; nt++) MMA_TF32(cacc[mt][nt], ua[mt], ub[nt]);
        }
        __syncthreads();
    }

#pragma unroll
    for (int mt = 0; mt < 2; mt++) {
        const int r0 = rowBase + wm0 + mt * 16 + g;
#pragma unroll
        for (int nt = 0; nt < NT; nt++) {
            const int cb = colBase + wn0 + nt * 8 + 2 * tig;
            float v0 = epi_apply<EPI>(cacc[mt][nt][0], cb, bias, nullptr, nullptr);
            float v1 = epi_apply<EPI>(cacc[mt][nt][1], cb + 1, bias, nullptr, nullptr);
            float v2 = epi_apply<EPI>(cacc[mt][nt][2], cb, bias, nullptr, nullptr);
            float v3 = epi_apply<EPI>(cacc[mt][nt][3], cb + 1, bias, nullptr, nullptr);
            *(float2*)&C[(size_t)r0 * ldc + cb] = make_float2(v0, v1);
            *(float2*)&C[(size_t)(r0 + 8) * ldc + cb] = make_float2(v2, v3);
        }
    }
}

// ---------------- weight permutes / rounded copies ----------------
__global__ void permute_w2(const float* __restrict__ c2w) {
    int idx = blockIdx.x * 256 + threadIdx.x;
    if (idx >= 256 * 1152) return;
    int co = idx / 1152, k = idx % 1152;
    int r = k >> 7, ci = k & 127;
    g_w2p[idx] = tf32r(c2w[co * 1152 + ci * 9 + r]);
}
__global__ void permute_wp(const float* __restrict__ pw) {
    int idx = blockIdx.x * 256 + threadIdx.x;
    if (idx >= 256 * 1024) return;
    int co = idx >> 10, k = idx & 1023;
    int r = k >> 8, ci = k & 255;
    g_wpp[idx] = tf32r(pw[(co << 10) + ci * 4 + r]);
}
__global__ void round_copy(const float* __restrict__ in, float* __restrict__ out, int n) {
    int idx = blockIdx.x * 256 + threadIdx.x;
    if (idx < n) out[idx] = tf32r(in[idx]);
}

// ---------------- TN FFMA SGEMM, 32x64 tile (x_proj): C = At^T * B^T --------
__global__ void __launch_bounds__(128)
sgemm_tn32(const float* __restrict__ At, int Mtot,
           const float* __restrict__ B, int ldb,
           float* __restrict__ C, int ldc, int K) {
    __shared__ __align__(16) float As[2][8][32];
    __shared__ __align__(16) float Bs[2][8][64];
    const int tid = threadIdx.x;
    const int rowBase = blockIdx.y * 32;
    const int tx = tid & 7, ty = tid >> 3;
    const int akr = tid >> 4, amc = (tid & 15) * 2;
    const int lRow = tid >> 1, lCol = (tid & 1) * 4;

    const float* Abase = At + (size_t)akr * Mtot + rowBase + amc;
    const float* Bb = B + (size_t)lRow * ldb + lCol;

    float acc[2][8];
#pragma unroll
    for (int i = 0; i < 2; i++)
#pragma unroll
        for (int j = 0; j < 8; j++) acc[i][j] = 0.f;

    float2 pa = *(const float2*)Abase;
    float4 pb = *(const float4*)Bb;
    *(float2*)&As[0][akr][amc] = pa;
    Bs[0][lCol + 0][lRow] = pb.x;
    Bs[0][lCol + 1][lRow] = pb.y;
    Bs[0][lCol + 2][lRow] = pb.z;
    Bs[0][lCol + 3][lRow] = pb.w;
    __syncthreads();

    int buf = 0;
    for (int k0 = 0; k0 < K; k0 += 8) {
        const bool more = (k0 + 8) < K;
        if (more) {
            pa = *(const float2*)(Abase + (size_t)(k0 + 8) * Mtot);
            pb = *(const float4*)(Bb + k0 + 8);
        }
#pragma unroll
        for (int kk = 0; kk < 8; kk++) {
            float ar[2], br[8];
            ar[0] = As[buf][kk][ty * 2];
            ar[1] = As[buf][kk][ty * 2 + 1];
            *(float4*)&br[0] = *(const float4*)&Bs[buf][kk][tx * 8];
            *(float4*)&br[4] = *(const float4*)&Bs[buf][kk][tx * 8 + 4];
#pragma unroll
            for (int i = 0; i < 2; i++)
#pragma unroll
                for (int j = 0; j < 8; j++) acc[i][j] = fmaf(ar[i], br[j], acc[i][j]);
        }
        if (more) {
            *(float2*)&As[buf ^ 1][akr][amc] = pa;
            Bs[buf ^ 1][lCol + 0][lRow] = pb.x;
            Bs[buf ^ 1][lCol + 1][lRow] = pb.y;
            Bs[buf ^ 1][lCol + 2][lRow] = pb.z;
            Bs[buf ^ 1][lCol + 3][lRow] = pb.w;
            __syncthreads();
            buf ^= 1;
        }
    }

#pragma unroll
    for (int i = 0; i < 2; i++) {
        const int r = rowBase + ty * 2 + i;
        float* crow = C + (size_t)r * ldc + tx * 8;
        *(float4*)&crow[0] = make_float4(acc[i][0], acc[i][1], acc[i][2], acc[i][3]);
        *(float4*)&crow[4] = make_float4(acc[i][4], acc[i][5], acc[i][6], acc[i][7]);
    }
}

// ---------------- conv stem ----------------
__global__ void conv1_kernel(const float* __restrict__ x, const float* __restrict__ w,
                             const float* __restrict__ bias, const float* __restrict__ g,
                             const float* __restrict__ bb) {
    int idx = blockIdx.x * 256 + threadIdx.x;
    if (idx >= 4 * 64 * 64 * 128) return;
    int co = idx & 127;
    int xx = (idx >> 7) & 63;
    int yy = (idx >> 13) & 63;
    int b = idx >> 19;
    float acc = bias[co];
#pragma unroll
    for (int ci = 0; ci < 3; ci++)
#pragma unroll
        for (int ky = 0; ky < 3; ky++) {
            int iy = yy + ky - 1;
            if ((unsigned)iy >= 64u) continue;
#pragma unroll
            for (int kx = 0; kx < 3; kx++) {
                int ix = xx + kx - 1;
                if ((unsigned)ix >= 64u) continue;
                acc += x[((b * 3 + ci) * 64 + iy) * 64 + ix] * w[((co * 3 + ci) * 3 + ky) * 3 + kx];
            }
        }
    float v = acc * (g[co] * rsqrtf(1.f + EPSV)) + bb[co];
    g_h1[idx] = tf32r(gelu_f(v));
}

// ---------------- mamba pieces ----------------
__global__ void __launch_bounds__(256) dwconv_t_kernel(const float* __restrict__ cw,
                                                       const float* __restrict__ cb) {
    __shared__ float sin[67][64];
    __shared__ float sout[64][65];
    const int r0g = blockIdx.x * 64;
    const int d0 = blockIdx.y * 64;
    const int tid = threadIdx.x;
    const int b = r0g >> 10;
    const int l0 = r0g & 1023;

    for (int idx = tid; idx < 67 * 64; idx += 256) {
        int rr = idx >> 6;
        int dc = idx & 63;
        int l = l0 + rr - 1;
        float v = 0.f;
        if ((unsigned)l < 1024u)
            v = g_xr[((size_t)(b * 1024 + l) << 10) + d0 + dc];
        sin[rr][dc] = v;
    }
    __syncthreads();

    const int dc = tid & 63;
    const int rbase = (tid >> 6) * 16;
    const float4 w = *(const float4*)&cw[(d0 + dc) * 4];
    const float bi = cb[d0 + dc];
#pragma unroll
    for (int o = 0; o < 16; o++) {
        int r = rbase + o;
        float acc = bi;
        acc = fmaf(sin[r + 0][dc], w.x, acc);
        acc = fmaf(sin[r + 1][dc], w.y, acc);
        acc = fmaf(sin[r + 2][dc], w.z, acc);
        acc = fmaf(sin[r + 3][dc], w.w, acc);
        sout[dc][r] = acc;
    }
    __syncthreads();

    for (int idx = tid; idx < 4096; idx += 256) {
        int dr = idx >> 6, rc = idx & 63;
        g_xlt[(size_t)(d0 + dr) * 4096 + r0g + rc] = sout[dr][rc];
    }
}

// Chunked scan with fused dt_proj + smem-cached operands: 1 block per (b,d).
__global__ void __launch_bounds__(256)
scan_kernel(const float* __restrict__ alog_l, const float* __restrict__ dssm_l,
            const float* __restrict__ dpw_l, const float* __restrict__ dpb_l) {
    const int d = blockIdx.x & 511;
    const int b = blockIdx.x >> 9;
    const int t = threadIdx.x;
    const int n = t & 15;
    const int c = t >> 4;

    __shared__ float sdelta[1024], su[1024], sres[1024];
    __shared__ float sw[32];
    __shared__ float sh_hend[16][16];
    __shared__ float sh_S[16];
    __shared__ float sh_y[1024];

    const float Adn = -__expf(alog_l[d * 16 + n]);
    const float Dd = dssm_l[d];
    const float dpb_d = dpb_l[d];

    if (t < 32) sw[t] = dpw_l[d * 32 + t];

    const size_t base = (size_t)d * 4096 + (size_t)b * 1024;
    *(float4*)&su[t * 4]   = *(const float4*)&g_xlt[base + t * 4];
    *(float4*)&sres[t * 4] = *(const float4*)&g_rest[base + t * 4];
    __syncthreads();

    // fused dt_proj: delta[row] = softplus(dpb[d] + xdbl[row][0..31] . dpw[d])
#pragma unroll
    for (int r4 = 0; r4 < 4; r4++) {
        const int row = t * 4 + r4;
        const float* xr = g_xdbl + ((size_t)(b * 1024 + row) << 6);
        float acc = dpb_d;
#pragma unroll
        for (int k4 = 0; k4 < 8; k4++) {
            float4 xv = *(const float4*)&xr[k4 * 4];
            acc = fmaf(xv.x, sw[k4 * 4 + 0], acc);
            acc = fmaf(xv.y, sw[k4 * 4 + 1], acc);
            acc = fmaf(xv.z, sw[k4 * 4 + 2], acc);
            acc = fmaf(xv.w, sw[k4 * 4 + 3], acc);
        }
        sdelta[row] = softplus_f(acc);
    }

    const int rb = b * 1024 + c * 64;
    const float* pB = g_xdbl + ((size_t)rb << 6) + 32 + n;
    const float* pC = g_xdbl + ((size_t)rb << 6) + 48 + n;
    __syncthreads();

    float h = 0.f, S = 0.f;
#pragma unroll 4
    for (int j = 0; j < 64; j++) {
        float dl = sdelta[c * 64 + j];
        float u  = su[c * 64 + j];
        float Bv = pB[j << 6];
        float a = __expf(dl * Adn);
        h = fmaf(a, h, dl * Bv * u);
        S += dl;
    }
    sh_hend[c][n] = h;
    if (n == 0) sh_S[c] = S;
    __syncthreads();

    float H0 = 0.f, Q = 0.f;
    for (int cp = c - 1; cp >= 0; cp--) {
        H0 = fmaf(sh_hend[cp][n], __expf(Adn * Q), H0);
        Q += sh_S[cp];
    }

    h = H0;
#pragma unroll 2
    for (int j = 0; j < 64; j++) {
        float dl = sdelta[c * 64 + j];
        float u  = su[c * 64 + j];
        float Bv = pB[j << 6];
        float Cv = pC[j << 6];
        float a = __expf(dl * Adn);
        h = fmaf(a, h, dl * Bv * u);
        float p = h * Cv;
        p += __shfl_xor_sync(0xFFFFFFFFu, p, 1);
        p += __shfl_xor_sync(0xFFFFFFFFu, p, 2);
        p += __shfl_xor_sync(0xFFFFFFFFu, p, 4);
        p += __shfl_xor_sync(0xFFFFFFFFu, p, 8);
        if (n == 0) {
            float sr = sres[c * 64 + j];
            sh_y[c * 64 + j] = tf32r((p + u * Dd) * sr);
        }
    }
    __syncthreads();

    *(float4*)&g_yt[base + t * 4] = *(float4*)&sh_y[t * 4];
}

// LN + residual add, warp-shuffle reductions; maintains rounded mirror g_sr
__global__ void ln_add_kernel(const float* __restrict__ w, const float* __restrict__ bi) {
    const int row = blockIdx.x;
    const int t = threadIdx.x;
    const int lane = t & 31, warp = t >> 5;
    __shared__ float shm[8], shv[8];
    float v = g_tmp[(size_t)row * 256 + t];

    float s = v;
#pragma unroll
    for (int o = 16; o > 0; o >>= 1) s += __shfl_xor_sync(0xFFFFFFFFu, s, o);
    if (lane == 0) shm[warp] = s;
    __syncthreads();
    float tot = shm[0] + shm[1] + shm[2] + shm[3] + shm[4] + shm[5] + shm[6] + shm[7];
    float mean = tot * (1.f / 256.f);

    float dv = v - mean;
    float q = dv * dv;
#pragma unroll
    for (int o = 16; o > 0; o >>= 1) q += __shfl_xor_sync(0xFFFFFFFFu, q, o);
    if (lane == 0) shv[warp] = q;
    __syncthreads();
    float vtot = shv[0] + shv[1] + shv[2] + shv[3] + shv[4] + shv[5] + shv[6] + shv[7];
    float var = vtot * (1.f / 256.f);

    float ns = g_s[(size_t)row * 256 + t] + dv * rsqrtf(var + EPSV) * w[t] + bi[t];
    g_s[(size_t)row * 256 + t] = ns;
    g_sr[(size_t)row * 256 + t] = tf32r(ns);
}

// ---------------- head ----------------
__global__ void head1_kernel() {
    int b = blockIdx.x >> 5, ch = blockIdx.x & 31, t = threadIdx.x;
    float acc = 0.f;
    const float* p = g_s + (size_t)((b << 10) + ch * 32) * 256 + t;
#pragma unroll 8
    for (int l = 0; l < 32; l++) acc += p[(size_t)l * 256];
    g_part[blockIdx.x * 256 + t] = acc;
}

__global__ void head2_kernel(const float* __restrict__ nw, const float* __restrict__ nb) {
    int b = blockIdx.x, t = threadIdx.x;
    float acc = 0.f;
#pragma unroll
    for (int c = 0; c < 32; c++) acc += g_part[((b << 5) + c) * 256 + t];
    float m = acc * (1.f / 1024.f);
    __shared__ float sh[256];
    sh[t] = m;
    __syncthreads();
    for (int o = 128; o > 0; o >>= 1) { if (t < o) sh[t] += sh[t + o]; __syncthreads(); }
    float mu = sh[0] * (1.f / 256.f);
    __syncthreads();
    float dv = m - mu;
    sh[t] = dv * dv;
    __syncthreads();
    for (int o = 128; o > 0; o >>= 1) { if (t < o) sh[t] += sh[t + o]; __syncthreads(); }
    float var = sh[0] * (1.f / 256.f);
    g_v[b * 256 + t] = dv * rsqrtf(var + EPSV) * nw[t] + nb[t];
}

__global__ void fc_kernel(const float* __restrict__ fcw, const float* __restrict__ fcb,
                          float* __restrict__ out) {
    int idx = blockIdx.x * 256 + threadIdx.x;
    if (idx >= 4000) return;
    int b = idx / 1000, n = idx % 1000;
    float acc = fcb[n];
    const float* v = g_v + b * 256;
    const float* w = fcw + n * 256;
#pragma unroll 8
    for (int k = 0; k < 256; k++) acc += v[k] * w[k];
    out[idx] = acc;
}

__global__ void softmax_kernel(float* __restrict__ out) {
    int b = blockIdx.x, t = threadIdx.x;
    __shared__ float sh[256];
    const float* lg = out + b * 1000;
    float mx = -1e30f;
    for (int i = t; i < 1000; i += 256) mx = fmaxf(mx, lg[i]);
    sh[t] = mx;
    __syncthreads();
    for (int o = 128; o > 0; o >>= 1) { if (t < o) sh[t] = fmaxf(sh[t], sh[t + o]); __syncthreads(); }
    mx = sh[0];
    __syncthreads();
    float s = 0.f;
    for (int i = t; i < 1000; i += 256) s += expf(lg[i] - mx);
    sh[t] = s;
    __syncthreads();
    for (int o = 128; o > 0; o >>= 1) { if (t < o) sh[t] += sh[t + o]; __syncthreads(); }
    float inv = 1.f / sh[0];
    for (int i = t; i < 1000; i += 256) out[4000 + b * 1000 + i] = expf(lg[i] - mx) * inv;
}

// ---------------- launch ----------------
extern "C" void kernel_launch(void* const* d_in, const int* in_sizes, int n_in,
                              void* d_out, int out_size) {
    const float* x    = (const float*)d_in[0];
    const float* c1w  = (const float*)d_in[1];
    const float* c1b  = (const float*)d_in[2];
    const float* g1   = (const float*)d_in[3];
    const float* b1   = (const float*)d_in[4];
    const float* c2w  = (const float*)d_in[5];
    const float* c2b  = (const float*)d_in[6];
    const float* g2   = (const float*)d_in[7];
    const float* b2   = (const float*)d_in[8];
    const float* pw   = (const float*)d_in[9];
    const float* pb   = (const float*)d_in[10];
    const float* g3   = (const float*)d_in[11];
    const float* b3   = (const float*)d_in[12];
    const float* ipw  = (const float*)d_in[13];
    const float* ipb  = (const float*)d_in[14];
    const float* cw   = (const float*)d_in[15];
    const float* cb   = (const float*)d_in[16];
    const float* xpw  = (const float*)d_in[17];
    const float* dpw  = (const float*)d_in[18];
    const float* dpb  = (const float*)d_in[19];
    const float* alog = (const float*)d_in[20];
    const float* dssm = (const float*)d_in[21];
    const float* opw  = (const float*)d_in[22];
    const float* opb  = (const float*)d_in[23];
    const float* lnw  = (const float*)d_in[24];
    const float* lnb  = (const float*)d_in[25];
    const float* nw   = (const float*)d_in[26];
    const float* nb   = (const float*)d_in[27];
    const float* fcw  = (const float*)d_in[28];
    const float* fcb  = (const float*)d_in[29];

    float *p_s, *p_sr, *p_xr, *p_xlt, *p_xdbl, *p_rest, *p_yt, *p_tmp;
    float *p_h2, *p_w2p, *p_wpp, *p_ipwr, *p_opwr;
    cudaGetSymbolAddress((void**)&p_s, g_s);
    cudaGetSymbolAddress((void**)&p_sr, g_sr);
    cudaGetSymbolAddress((void**)&p_xr, g_xr);
    cudaGetSymbolAddress((void**)&p_xlt, g_xlt);
    cudaGetSymbolAddress((void**)&p_xdbl, g_xdbl);
    cudaGetSymbolAddress((void**)&p_rest, g_rest);
    cudaGetSymbolAddress((void**)&p_yt, g_yt);
    cudaGetSymbolAddress((void**)&p_tmp, g_tmp);
    cudaGetSymbolAddress((void**)&p_h2, g_h2);
    cudaGetSymbolAddress((void**)&p_w2p, g_w2p);
    cudaGetSymbolAddress((void**)&p_wpp, g_wpp);
    cudaGetSymbolAddress((void**)&p_ipwr, g_ipwr);
    cudaGetSymbolAddress((void**)&p_opwr, g_opwr);

    constexpr int SM128 = 2 * 128 * 144 + 2 * 128 * 144;       // 73728
    constexpr int SM64 = 2 * 64 * 144 + 2 * 128 * 144;         // 55296
    constexpr int SMTN64 = 2 * (32 * 72 * 4) + 2 * 18432;      // 55296
    cudaFuncSetAttribute(mm_gemm<128, 1, 2, 0, 1, 0>, cudaFuncAttributeMaxDynamicSharedMemorySize, SM128);
    cudaFuncSetAttribute(mm_gemm<64, 2, 2, 0, 0, 1>, cudaFuncAttributeMaxDynamicSharedMemorySize, SM64);
    cudaFuncSetAttribute(mm_gemm<128, 0, 4, 0, 0, 2>, cudaFuncAttributeMaxDynamicSharedMemorySize, SM128);
    cudaFuncSetAttribute(mm_gemm_tn<64, 1>, cudaFuncAttributeMaxDynamicSharedMemorySize, SMTN64);

    // ---- one-time weight prep ----
    permute_w2<<<(256 * 1152 + 255) / 256, 256>>>(c2w);
    permute_wp<<<(256 * 1024 + 255) / 256, 256>>>(pw);
    round_copy<<<(4 * 1024 * 256 + 255) / 256, 256>>>(ipw, p_ipwr, 4 * 1024 * 256);
    round_copy<<<(4 * 256 * 512 + 255) / 256, 256>>>(opw, p_opwr, 4 * 256 * 512);

    // ---- stem ----
    conv1_kernel<<<8192, 256>>>(x, c1w, c1b, g1, b1);
    mm_gemm<128, 1, 2, 0, 1, 0><<<dim3(2, 128), 256, SM128>>>(
        nullptr, 0, p_w2p, 1152, p_h2, 256, 1152, c2b, g2, b2, nullptr, 0);
    // patchify: writes fp32 g_s + rounded mirror g_sr
    mm_gemm<64, 2, 2, 0, 0, 1><<<dim3(2, 64), 256, SM64>>>(
        nullptr, 0, p_wpp, 1024, p_s, 256, 1024, pb, g3, b3, p_sr, 0);

    // ---- mamba layers ----
    for (int i = 0; i < 4; i++) {
        const float* ipw_l  = p_ipwr + (size_t)i * 1024 * 256;
        const float* ipb_l  = ipb + (size_t)i * 1024;
        const float* cw_l   = cw + (size_t)i * 512 * 4;
        const float* cb_l   = cb + (size_t)i * 512;
        const float* xpw_l  = xpw + (size_t)i * 64 * 512;
        const float* dpw_l  = dpw + (size_t)i * 512 * 32;
        const float* dpb_l  = dpb + (size_t)i * 512;
        const float* alog_l = alog + (size_t)i * 512 * 16;
        const float* dssm_l = dssm + (size_t)i * 512;
        const float* opw_l  = p_opwr + (size_t)i * 256 * 512;
        const float* opb_l  = opb + (size_t)i * 256;
        const float* lnw_l  = lnw + (size_t)i * 256;
        const float* lnb_l  = lnb + (size_t)i * 256;

        // in_proj (tf32 mma, A pre-rounded g_sr): xi -> g_xr, silu(res) -> g_rest^T
        mm_gemm<128, 0, 4, 0, 0, 2><<<dim3(8, 32), 256, SM128>>>(
            p_sr, 256, ipw_l, 256, p_xr, 1024, 256, ipb_l, nullptr, nullptr,
            p_rest, 4096);
        dwconv_t_kernel<<<dim3(64, 8), 256>>>(cw_l, cb_l);
        // x_proj (TN FFMA, 32-row tiles)
        sgemm_tn32<<<dim3(1, 128), 128>>>(p_xlt, 4096, xpw_l, 512, p_xdbl, 64, 512);
        // scan with fused dt_proj
        scan_kernel<<<2048, 256>>>(alog_l, dssm_l, dpw_l, dpb_l);
        // out_proj (TN tf32 mma, A = g_yt K-major)
        mm_gemm_tn<64, 1><<<dim3(2, 64), 256, SMTN64>>>(p_yt, 4096, opw_l, 512,
                                                        p_tmp, 256, 512, opb_l);
        ln_add_kernel<<<4096, 256>>>(lnw_l, lnb_l);
    }

    // ---- head ----
    head1_kernel<<<128, 256>>>();
    head2_kernel<<<4, 256>>>(nw, nb);
    fc_kernel<<<16, 256>>>(fcw, fcb, (float*)d_out);
    if (out_size >= 8000) softmax_kernel<<<4, 256>>>((float*)d_out);
}

// round 12
// speedup vs baseline: 1.4155x; 1.4155x over previous
#include <cuda_runtime.h>
#include <math.h>
#include <stdint.h>

#define EPSV 1e-5f

// ---------------- scratch (static device globals; no allocs) ----------------
__device__ float g_h1[4 * 64 * 64 * 128];    // conv1 out, NHWC (tf32-rounded)
__device__ float g_h2[16384 * 256];          // conv2 out, NHWC (tf32-rounded)
__device__ float g_s[4096 * 256];            // sequence [b*l, dm] (full fp32)
__device__ float g_sr[4096 * 256];           // tf32-rounded mirror of g_s
__device__ float g_xr[4096 * 1024];          // in_proj out, xi half (cols 0..511)
__device__ float g_xlt[512 * 4096];          // depthwise conv out, TRANSPOSED [d][row]
__device__ float g_xdbl[4096 * 64];          // x_proj out (dt|B|C)
__device__ float g_deltat[512 * 4096];       // softplus(dt_proj), TRANSPOSED [d][row]
__device__ float g_rest[512 * 4096];         // silu(res), TRANSPOSED [d][row]
__device__ float g_yt[512 * 4096];           // scan out, TRANSPOSED [d][row], tf32-rounded
__device__ float g_tmp[4096 * 256];          // out_proj out
__device__ float g_part[128 * 256];          // head partials
__device__ float g_v[4 * 256];               // pooled+LN features
__device__ float g_w2p[256 * 1152];          // permuted conv2 weights (tf32-rounded)
__device__ float g_wpp[256 * 1024];          // permuted patchify weights (tf32-rounded)
__device__ float g_ipwr[4 * 1024 * 256];     // rounded in_proj weights
__device__ float g_opwr[4 * 256 * 512];      // rounded out_proj weights

__device__ __forceinline__ float gelu_f(float v) {
    return 0.5f * v * (1.f + erff(v * 0.70710678118654752440f));
}
__device__ __forceinline__ float softplus_f(float x) {
    return fmaxf(x, 0.f) + log1pf(expf(-fabsf(x)));
}
__device__ __forceinline__ uint32_t cvt_tf32(float f) {
    uint32_t r;
    asm("cvt.rna.tf32.f32 %0, %1;" : "=r"(r) : "f"(f));
    return r;
}
__device__ __forceinline__ float tf32r(float f) {
    return __uint_as_float(cvt_tf32(f));
}

// ---------------- A-tile source: 0=plain, 1=conv3x3 on g_h1, 2=patchify g_h2 -
template <int AMODE>
__device__ __forceinline__ void srcA(const float* __restrict__ A, int lda,
                                     int gr, int gk, const float*& p, int& sz) {
    if (AMODE == 0) {
        p = A + (size_t)gr * lda + gk;
        sz = 16;
    } else if (AMODE == 1) {
        int b = gr >> 12, yy = (gr >> 6) & 63, xx = gr & 63;
        int r = gk >> 7, ci = gk & 127;
        int ky = r / 3, kx = r - ky * 3;
        int iy = yy + ky - 1, ix = xx + kx - 1;
        if ((unsigned)iy < 64u && (unsigned)ix < 64u) {
            p = &g_h1[(((b * 64 + iy) * 64 + ix) << 7) + ci];
            sz = 16;
        } else {
            p = g_h1;
            sz = 0;
        }
    } else {
        int b = gr >> 10, oy = (gr >> 5) & 31, ox = gr & 31;
        int r = gk >> 8, ci = gk & 255;
        int ky = r >> 1, kx = r & 1;
        p = &g_h2[(((b * 64 + 2 * oy + ky) * 64 + 2 * ox + kx) << 8) + ci];
        sz = 16;
    }
}

__device__ __forceinline__ void cpasync16(uint32_t dst, const void* src, int srcsz) {
    asm volatile("cp.async.cg.shared.global [%0], [%1], 16, %2;"
                 :: "r"(dst), "l"(src), "r"(srcsz));
}

template <int EPI>
__device__ __forceinline__ float epi_apply(float v, int c,
                                           const float* __restrict__ bias,
                                           const float* __restrict__ bn_g,
                                           const float* __restrict__ bn_b) {
    if (EPI == 1) v += bias[c];
    else if (EPI == 2) {
        v += bias[c];
        v = v * (bn_g[c] * rsqrtf(1.f + EPSV)) + bn_b[c];
        v = gelu_f(v);
    } else if (EPI == 4) {
        v += bias[c];
        if (c >= 512) v = v * __frcp_rn(1.f + __expf(-v));
    }
    return v;
}

#define MMA_TF32(acc, ua, ub)                                              \
    asm volatile(                                                          \
        "mma.sync.aligned.m16n8k8.row.col.f32.tf32.tf32.f32 "              \
        "{%0,%1,%2,%3}, {%4,%5,%6,%7}, {%8,%9}, {%0,%1,%2,%3};"            \
        : "+f"((acc)[0]), "+f"((acc)[1]), "+f"((acc)[2]), "+f"((acc)[3])   \
        : "r"((ua)[0]), "r"((ua)[1]), "r"((ua)[2]), "r"((ua)[3]),          \
          "r"((ub)[0]), "r"((ub)[1]))

// =========== tf32 mma.sync GEMM (NT): C[M,N] = A[M,K] * B[N,K]^T ============
// WMODE: 0=plain C write (with OUTR), 1=C + tf32-rounded mirror into Caux,
//        2=split: c<512 -> C row-major, c>=512 -> Caux[(c-512)*aux_ld + r]
template <int BM, int AMODE, int EPI, int CVTA, int OUTR, int WMODE>
__global__ void __launch_bounds__(256)
mm_gemm(const float* __restrict__ A, int lda,
        const float* __restrict__ B, int ldb,
        float* __restrict__ C, int ldc, int K,
        const float* __restrict__ bias,
        const float* __restrict__ bn_g, const float* __restrict__ bn_b,
        float* __restrict__ Caux, int aux_ld) {
    constexpr int WARPS_M = BM / 32;
    constexpr int WARPS_N = 8 / WARPS_M;
    constexpr int WN = 128 / WARPS_N;
    constexpr int NT = WN / 8;
    constexpr int AITER = BM / 32;

    extern __shared__ float sm[];
    const uint32_t sbase = (uint32_t)__cvta_generic_to_shared(sm);
    const int tid = threadIdx.x;
    const int warp = tid >> 5, lane = tid & 31;
    const int g = lane >> 2, tig = lane & 3;
    const int warpM = warp % WARPS_M, warpN = warp / WARPS_M;
    const int wm0 = warpM * 32, wn0 = warpN * WN;
    const int rowBase = blockIdx.y * BM, colBase = blockIdx.x * 128;

    float cacc[2][NT][4];
#pragma unroll
    for (int mt = 0; mt < 2; mt++)
#pragma unroll
        for (int nt = 0; nt < NT; nt++)
#pragma unroll
            for (int q = 0; q < 4; q++) cacc[mt][nt][q] = 0.f;

    const int nch = K >> 5;

    auto load_chunk = [&](int ch, int buf) {
        const int k0 = ch << 5;
        const uint32_t aBase = sbase + buf * (BM * 144);
        const uint32_t bBase = sbase + 2 * (BM * 144) + buf * 18432;
#pragma unroll
        for (int i = 0; i < AITER; i++) {
            int u = tid + i * 256;
            int row = u >> 3, c16 = u & 7;
            const float* p;
            int sz;
            srcA<AMODE>(A, lda, rowBase + row, k0 + c16 * 4, p, sz);
            cpasync16(aBase + row * 144 + c16 * 16, p, sz);
        }
#pragma unroll
        for (int i = 0; i < 4; i++) {
            int u = tid + i * 256;
            int row = u >> 3, c16 = u & 7;
            const float* p = B + (size_t)(colBase + row) * ldb + k0 + c16 * 4;
            cpasync16(bBase + row * 144 + c16 * 16, p, 16);
        }
        asm volatile("cp.async.commit_group;");
    };

    load_chunk(0, 0);
    for (int ch = 0; ch < nch; ch++) {
        const int buf = ch & 1;
        if (ch + 1 < nch) {
            load_chunk(ch + 1, buf ^ 1);
            asm volatile("cp.async.wait_group 1;" ::: "memory");
        } else {
            asm volatile("cp.async.wait_group 0;" ::: "memory");
        }
        __syncthreads();

        const float* asb = sm + buf * (BM * 36);
        const float* bsb = sm + 2 * (BM * 36) + buf * 4608;
#pragma unroll
        for (int ks = 0; ks < 4; ks++) {
            uint32_t ua[2][4];
#pragma unroll
            for (int mt = 0; mt < 2; mt++) {
                const float* Ab = asb + (wm0 + mt * 16 + g) * 36 + ks * 8 + tig;
                if (CVTA) {
                    ua[mt][0] = cvt_tf32(Ab[0]);
                    ua[mt][1] = cvt_tf32(Ab[288]);
                    ua[mt][2] = cvt_tf32(Ab[4]);
                    ua[mt][3] = cvt_tf32(Ab[292]);
                } else {
                    ua[mt][0] = __float_as_uint(Ab[0]);
                    ua[mt][1] = __float_as_uint(Ab[288]);
                    ua[mt][2] = __float_as_uint(Ab[4]);
                    ua[mt][3] = __float_as_uint(Ab[292]);
                }
            }
            uint32_t ub[NT][2];
#pragma unroll
            for (int nt = 0; nt < NT; nt++) {
                const float* Bb = bsb + (wn0 + nt * 8 + g) * 36 + ks * 8 + tig;
                ub[nt][0] = __float_as_uint(Bb[0]);
                ub[nt][1] = __float_as_uint(Bb[4]);
            }
#pragma unroll
            for (int mt = 0; mt < 2; mt++)
#pragma unroll
                for (int nt = 0; nt < NT; nt++) MMA_TF32(cacc[mt][nt], ua[mt], ub[nt]);
        }
        __syncthreads();
    }

#pragma unroll
    for (int mt = 0; mt < 2; mt++) {
        const int r0 = rowBase + wm0 + mt * 16 + g;
#pragma unroll
        for (int nt = 0; nt < NT; nt++) {
            const int cb = colBase + wn0 + nt * 8 + 2 * tig;
            float v0 = epi_apply<EPI>(cacc[mt][nt][0], cb, bias, bn_g, bn_b);
            float v1 = epi_apply<EPI>(cacc[mt][nt][1], cb + 1, bias, bn_g, bn_b);
            float v2 = epi_apply<EPI>(cacc[mt][nt][2], cb, bias, bn_g, bn_b);
            float v3 = epi_apply<EPI>(cacc[mt][nt][3], cb + 1, bias, bn_g, bn_b);
            if (WMODE == 0) {
                if (OUTR) {
                    v0 = tf32r(v0); v1 = tf32r(v1); v2 = tf32r(v2); v3 = tf32r(v3);
                }
                *(float2*)&C[(size_t)r0 * ldc + cb] = make_float2(v0, v1);
                *(float2*)&C[(size_t)(r0 + 8) * ldc + cb] = make_float2(v2, v3);
            } else if (WMODE == 1) {
                *(float2*)&C[(size_t)r0 * ldc + cb] = make_float2(v0, v1);
                *(float2*)&C[(size_t)(r0 + 8) * ldc + cb] = make_float2(v2, v3);
                *(float2*)&Caux[(size_t)r0 * ldc + cb] = make_float2(tf32r(v0), tf32r(v1));
                *(float2*)&Caux[(size_t)(r0 + 8) * ldc + cb] = make_float2(tf32r(v2), tf32r(v3));
            } else {
                if (cb < 512) {
                    *(float2*)&C[(size_t)r0 * ldc + cb] = make_float2(v0, v1);
                    *(float2*)&C[(size_t)(r0 + 8) * ldc + cb] = make_float2(v2, v3);
                } else {
                    const int d0 = cb - 512;
                    Caux[(size_t)d0 * aux_ld + r0] = v0;
                    Caux[(size_t)(d0 + 1) * aux_ld + r0] = v1;
                    Caux[(size_t)d0 * aux_ld + r0 + 8] = v2;
                    Caux[(size_t)(d0 + 1) * aux_ld + r0 + 8] = v3;
                }
            }
        }
    }
}

// =========== tf32 mma.sync GEMM (TN): C[M,N] = At^T * B^T ===================
template <int BM, int EPI>
__global__ void __launch_bounds__(256)
mm_gemm_tn(const float* __restrict__ At, int Mtot,
           const float* __restrict__ B, int ldb,
           float* __restrict__ C, int ldc, int K,
           const float* __restrict__ bias) {
    constexpr int WARPS_M = BM / 32;
    constexpr int WARPS_N = 8 / WARPS_M;
    constexpr int WN = 128 / WARPS_N;
    constexpr int NT = WN / 8;
    constexpr int AST = BM + 8;
    constexpr int ABUF = 32 * AST * 4;
    constexpr int AUNITS = (32 * BM) / 4;
    constexpr int AITER = AUNITS / 256;
    constexpr int UPR = BM / 4;

    extern __shared__ float sm[];
    const uint32_t sbase = (uint32_t)__cvta_generic_to_shared(sm);
    const int tid = threadIdx.x;
    const int warp = tid >> 5, lane = tid & 31;
    const int g = lane >> 2, tig = lane & 3;
    const int warpM = warp % WARPS_M, warpN = warp / WARPS_M;
    const int wm0 = warpM * 32, wn0 = warpN * WN;
    const int rowBase = blockIdx.y * BM, colBase = blockIdx.x * 128;

    float cacc[2][NT][4];
#pragma unroll
    for (int mt = 0; mt < 2; mt++)
#pragma unroll
        for (int nt = 0; nt < NT; nt++)
#pragma unroll
            for (int q = 0; q < 4; q++) cacc[mt][nt][q] = 0.f;

    const int nch = K >> 5;

    auto load_chunk = [&](int ch, int buf) {
        const int k0 = ch << 5;
        const uint32_t aBase = sbase + buf * ABUF;
        const uint32_t bBase = sbase + 2 * ABUF + buf * 18432;
#pragma unroll
        for (int i = 0; i < AITER; i++) {
            int u = tid + i * 256;
            int k = u / UPR, mu = u % UPR;
            const float* p = At + (size_t)(k0 + k) * Mtot + rowBase + mu * 4;
            cpasync16(aBase + k * (AST * 4) + mu * 16, p, 16);
        }
#pragma unroll
        for (int i = 0; i < 4; i++) {
            int u = tid + i * 256;
            int row = u >> 3, c16 = u & 7;
            const float* p = B + (size_t)(colBase + row) * ldb + k0 + c16 * 4;
            cpasync16(bBase + row * 144 + c16 * 16, p, 16);
        }
        asm volatile("cp.async.commit_group;");
    };

    load_chunk(0, 0);
    for (int ch = 0; ch < nch; ch++) {
        const int buf = ch & 1;
        if (ch + 1 < nch) {
            load_chunk(ch + 1, buf ^ 1);
            asm volatile("cp.async.wait_group 1;" ::: "memory");
        } else {
            asm volatile("cp.async.wait_group 0;" ::: "memory");
        }
        __syncthreads();

        const float* asb = sm + buf * (32 * AST);
        const float* bsb = sm + 2 * (32 * AST) + buf * 4608;
#pragma unroll
        for (int ks = 0; ks < 4; ks++) {
            uint32_t ua[2][4];
#pragma unroll
            for (int mt = 0; mt < 2; mt++) {
                const int m0 = wm0 + mt * 16 + g;
                const float* Ab = asb + (ks * 8 + tig) * AST + m0;
                ua[mt][0] = __float_as_uint(Ab[0]);
                ua[mt][1] = __float_as_uint(Ab[8]);
                ua[mt][2] = __float_as_uint(Ab[4 * AST]);
                ua[mt][3] = __float_as_uint(Ab[4 * AST + 8]);
            }
            uint32_t ub[NT][2];
#pragma unroll
            for (int nt = 0; nt < NT; nt++) {
                const float* Bb = bsb + (wn0 + nt * 8 + g) * 36 + ks * 8 + tig;
                ub[nt][0] = __float_as_uint(Bb[0]);
                ub[nt][1] = __float_as_uint(Bb[4]);
            }
#pragma unroll
            for (int mt = 0; mt < 2; mt++)
#pragma unroll
                for (int nt = 0; nt < NT; nt++) MMA_TF32(cacc[mt][nt], ua[mt], ub[nt]);
        }
        __syncthreads();
    }

#pragma unroll
    for (int mt = 0; mt < 2; mt++) {
        const int r0 = rowBase + wm0 + mt * 16 + g;
#pragma unroll
        for (int nt = 0; nt < NT; nt++) {
            const int cb = colBase + wn0 + nt * 8 + 2 * tig;
            float v0 = epi_apply<EPI>(cacc[mt][nt][0], cb, bias, nullptr, nullptr);
            float v1 = epi_apply<EPI>(cacc[mt][nt][1], cb + 1, bias, nullptr, nullptr);
            float v2 = epi_apply<EPI>(cacc[mt][nt][2], cb, bias, nullptr, nullptr);
            float v3 = epi_apply<EPI>(cacc[mt][nt][3], cb + 1, bias, nullptr, nullptr);
            *(float2*)&C[(size_t)r0 * ldc + cb] = make_float2(v0, v1);
            *(float2*)&C[(size_t)(r0 + 8) * ldc + cb] = make_float2(v2, v3);
        }
    }
}

// ---------------- fused weight prep (permutes + rounded copies) -------------
__global__ void prep_kernel(const float* __restrict__ c2w, const float* __restrict__ pw,
                            const float* __restrict__ ipw, const float* __restrict__ opw) {
    int idx = blockIdx.x * 256 + threadIdx.x;
    // [0, 294912): permute conv2 weights
    if (idx < 256 * 1152) {
        int co = idx / 1152, k = idx % 1152;
        int r = k >> 7, ci = k & 127;
        g_w2p[idx] = tf32r(c2w[co * 1152 + ci * 9 + r]);
        return;
    }
    idx -= 256 * 1152;
    // [0, 262144): permute patchify weights
    if (idx < 256 * 1024) {
        int co = idx >> 10, k = idx & 1023;
        int r = k >> 8, ci = k & 255;
        g_wpp[idx] = tf32r(pw[(co << 10) + ci * 4 + r]);
        return;
    }
    idx -= 256 * 1024;
    // [0, 1048576): round in_proj weights
    if (idx < 4 * 1024 * 256) {
        g_ipwr[idx] = tf32r(ipw[idx]);
        return;
    }
    idx -= 4 * 1024 * 256;
    // [0, 524288): round out_proj weights
    if (idx < 4 * 256 * 512) g_opwr[idx] = tf32r(opw[idx]);
}

// ---------------- FFMA SGEMM (dt_proj). EPI: 5=softplus(+bias[r]) ----------
template <int BM, int BN, int TM, int TN, int EPI>
__global__ void __launch_bounds__((BM / TM) * (BN / TN))
sgemm_nt(const float* __restrict__ A, int lda,
         const float* __restrict__ B, int ldb,
         float* __restrict__ C, int ldc,
         int K,
         const float* __restrict__ bias) {
    constexpr int BK = 8;
    constexpr int NT = (BM / TM) * (BN / TN);
    constexpr int AROWS = NT / 2;
    constexpr int NLA = BM / AROWS;
    constexpr int BROWS = NT / 2;
    constexpr int NLB = BN / BROWS;

    __shared__ __align__(16) float As[2][BK][BM];
    __shared__ __align__(16) float Bs[2][BK][BN];

    const int tid = threadIdx.x;
    const int rowBase = blockIdx.y * BM;
    const int colBase = blockIdx.x * BN;
    const int tx = tid % (BN / TN);
    const int ty = tid / (BN / TN);
    const int lRow = tid >> 1;
    const int lCol = (tid & 1) * 4;

    const float* Ab = A + (size_t)(rowBase + lRow) * lda + lCol;
    const float* Bb = B + (size_t)(colBase + lRow) * ldb + lCol;

    float acc[TM][TN];
#pragma unroll
    for (int i = 0; i < TM; i++)
#pragma unroll
        for (int j = 0; j < TN; j++) acc[i][j] = 0.f;

    float4 pa[NLA], pb[NLB];
#pragma unroll
    for (int p = 0; p < NLA; p++)
        pa[p] = *(const float4*)(Ab + (size_t)p * AROWS * lda);
#pragma unroll
    for (int p = 0; p < NLB; p++)
        pb[p] = *(const float4*)(Bb + (size_t)p * BROWS * ldb);
#pragma unroll
    for (int p = 0; p < NLA; p++) {
        As[0][lCol + 0][lRow + p * AROWS] = pa[p].x;
        As[0][lCol + 1][lRow + p * AROWS] = pa[p].y;
        As[0][lCol + 2][lRow + p * AROWS] = pa[p].z;
        As[0][lCol + 3][lRow + p * AROWS] = pa[p].w;
    }
#pragma unroll
    for (int p = 0; p < NLB; p++) {
        Bs[0][lCol + 0][lRow + p * BROWS] = pb[p].x;
        Bs[0][lCol + 1][lRow + p * BROWS] = pb[p].y;
        Bs[0][lCol + 2][lRow + p * BROWS] = pb[p].z;
        Bs[0][lCol + 3][lRow + p * BROWS] = pb[p].w;
    }
    __syncthreads();

    int buf = 0;
    for (int k0 = 0; k0 < K; k0 += BK) {
        const bool more = (k0 + BK) < K;
        if (more) {
#pragma unroll
            for (int p = 0; p < NLA; p++)
                pa[p] = *(const float4*)(Ab + (size_t)p * AROWS * lda + k0 + BK);
#pragma unroll
            for (int p = 0; p < NLB; p++)
                pb[p] = *(const float4*)(Bb + (size_t)p * BROWS * ldb + k0 + BK);
        }
#pragma unroll
        for (int kk = 0; kk < BK; kk++) {
            float ar[TM], br[TN];
#pragma unroll
            for (int i = 0; i < TM; i += 4)
                *(float4*)&ar[i] = *(const float4*)&As[buf][kk][ty * TM + i];
#pragma unroll
            for (int j = 0; j < TN; j += 4)
                *(float4*)&br[j] = *(const float4*)&Bs[buf][kk][tx * TN + j];
#pragma unroll
            for (int i = 0; i < TM; i++)
#pragma unroll
                for (int j = 0; j < TN; j++) acc[i][j] = fmaf(ar[i], br[j], acc[i][j]);
        }
        if (more) {
#pragma unroll
            for (int p = 0; p < NLA; p++) {
                As[buf ^ 1][lCol + 0][lRow + p * AROWS] = pa[p].x;
                As[buf ^ 1][lCol + 1][lRow + p * AROWS] = pa[p].y;
                As[buf ^ 1][lCol + 2][lRow + p * AROWS] = pa[p].z;
                As[buf ^ 1][lCol + 3][lRow + p * AROWS] = pa[p].w;
            }
#pragma unroll
            for (int p = 0; p < NLB; p++) {
                Bs[buf ^ 1][lCol + 0][lRow + p * BROWS] = pb[p].x;
                Bs[buf ^ 1][lCol + 1][lRow + p * BROWS] = pb[p].y;
                Bs[buf ^ 1][lCol + 2][lRow + p * BROWS] = pb[p].z;
                Bs[buf ^ 1][lCol + 3][lRow + p * BROWS] = pb[p].w;
            }
            __syncthreads();
            buf ^= 1;
        }
    }

#pragma unroll
    for (int i = 0; i < TM; i++) {
        const int r = rowBase + ty * TM + i;
        float* crow = C + (size_t)r * ldc + colBase + tx * TN;
#pragma unroll
        for (int j4 = 0; j4 < TN; j4 += 4) {
            float vv[4];
#pragma unroll
            for (int j = 0; j < 4; j++) {
                float v = acc[i][j4 + j];
                if (EPI == 5) v = softplus_f(v + bias[r]);
                vv[j] = v;
            }
            *(float4*)&crow[j4] = make_float4(vv[0], vv[1], vv[2], vv[3]);
        }
    }
}

// ---------------- TN FFMA SGEMM, 32x64 tile (x_proj): C = At^T * B^T --------
__global__ void __launch_bounds__(128)
sgemm_tn32(const float* __restrict__ At, int Mtot,
           const float* __restrict__ B, int ldb,
           float* __restrict__ C, int ldc, int K) {
    __shared__ __align__(16) float As[2][8][32];
    __shared__ __align__(16) float Bs[2][8][64];
    const int tid = threadIdx.x;
    const int rowBase = blockIdx.y * 32;
    const int tx = tid & 7, ty = tid >> 3;
    const int akr = tid >> 4, amc = (tid & 15) * 2;
    const int lRow = tid >> 1, lCol = (tid & 1) * 4;

    const float* Abase = At + (size_t)akr * Mtot + rowBase + amc;
    const float* Bb = B + (size_t)lRow * ldb + lCol;

    float acc[2][8];
#pragma unroll
    for (int i = 0; i < 2; i++)
#pragma unroll
        for (int j = 0; j < 8; j++) acc[i][j] = 0.f;

    float2 pa = *(const float2*)Abase;
    float4 pb = *(const float4*)Bb;
    *(float2*)&As[0][akr][amc] = pa;
    Bs[0][lCol + 0][lRow] = pb.x;
    Bs[0][lCol + 1][lRow] = pb.y;
    Bs[0][lCol + 2][lRow] = pb.z;
    Bs[0][lCol + 3][lRow] = pb.w;
    __syncthreads();

    int buf = 0;
    for (int k0 = 0; k0 < K; k0 += 8) {
        const bool more = (k0 + 8) < K;
        if (more) {
            pa = *(const float2*)(Abase + (size_t)(k0 + 8) * Mtot);
            pb = *(const float4*)(Bb + k0 + 8);
        }
#pragma unroll
        for (int kk = 0; kk < 8; kk++) {
            float ar[2], br[8];
            ar[0] = As[buf][kk][ty * 2];
            ar[1] = As[buf][kk][ty * 2 + 1];
            *(float4*)&br[0] = *(const float4*)&Bs[buf][kk][tx * 8];
            *(float4*)&br[4] = *(const float4*)&Bs[buf][kk][tx * 8 + 4];
#pragma unroll
            for (int i = 0; i < 2; i++)
#pragma unroll
                for (int j = 0; j < 8; j++) acc[i][j] = fmaf(ar[i], br[j], acc[i][j]);
        }
        if (more) {
            *(float2*)&As[buf ^ 1][akr][amc] = pa;
            Bs[buf ^ 1][lCol + 0][lRow] = pb.x;
            Bs[buf ^ 1][lCol + 1][lRow] = pb.y;
            Bs[buf ^ 1][lCol + 2][lRow] = pb.z;
            Bs[buf ^ 1][lCol + 3][lRow] = pb.w;
            __syncthreads();
            buf ^= 1;
        }
    }

#pragma unroll
    for (int i = 0; i < 2; i++) {
        const int r = rowBase + ty * 2 + i;
        float* crow = C + (size_t)r * ldc + tx * 8;
        *(float4*)&crow[0] = make_float4(acc[i][0], acc[i][1], acc[i][2], acc[i][3]);
        *(float4*)&crow[4] = make_float4(acc[i][4], acc[i][5], acc[i][6], acc[i][7]);
    }
}

// ---------------- conv stem ----------------
__global__ void conv1_kernel(const float* __restrict__ x, const float* __restrict__ w,
                             const float* __restrict__ bias, const float* __restrict__ g,
                             const float* __restrict__ bb) {
    int idx = blockIdx.x * 256 + threadIdx.x;
    if (idx >= 4 * 64 * 64 * 128) return;
    int co = idx & 127;
    int xx = (idx >> 7) & 63;
    int yy = (idx >> 13) & 63;
    int b = idx >> 19;
    float acc = bias[co];
#pragma unroll
    for (int ci = 0; ci < 3; ci++)
#pragma unroll
        for (int ky = 0; ky < 3; ky++) {
            int iy = yy + ky - 1;
            if ((unsigned)iy >= 64u) continue;
#pragma unroll
            for (int kx = 0; kx < 3; kx++) {
                int ix = xx + kx - 1;
                if ((unsigned)ix >= 64u) continue;
                acc += x[((b * 3 + ci) * 64 + iy) * 64 + ix] * w[((co * 3 + ci) * 3 + ky) * 3 + kx];
            }
        }
    float v = acc * (g[co] * rsqrtf(1.f + EPSV)) + bb[co];
    g_h1[idx] = tf32r(gelu_f(v));
}

// ---------------- mamba pieces ----------------
__global__ void __launch_bounds__(256) dwconv_t_kernel(const float* __restrict__ cw,
                                                       const float* __restrict__ cb) {
    __shared__ float sin[67][64];
    __shared__ float sout[64][65];
    const int r0g = blockIdx.x * 64;
    const int d0 = blockIdx.y * 64;
    const int tid = threadIdx.x;
    const int b = r0g >> 10;
    const int l0 = r0g & 1023;

    for (int idx = tid; idx < 67 * 64; idx += 256) {
        int rr = idx >> 6;
        int dc = idx & 63;
        int l = l0 + rr - 1;
        float v = 0.f;
        if ((unsigned)l < 1024u)
            v = g_xr[((size_t)(b * 1024 + l) << 10) + d0 + dc];
        sin[rr][dc] = v;
    }
    __syncthreads();

    const int dc = tid & 63;
    const int rbase = (tid >> 6) * 16;
    const float4 w = *(const float4*)&cw[(d0 + dc) * 4];
    const float bi = cb[d0 + dc];
#pragma unroll
    for (int o = 0; o < 16; o++) {
        int r = rbase + o;
        float acc = bi;
        acc = fmaf(sin[r + 0][dc], w.x, acc);
        acc = fmaf(sin[r + 1][dc], w.y, acc);
        acc = fmaf(sin[r + 2][dc], w.z, acc);
        acc = fmaf(sin[r + 3][dc], w.w, acc);
        sout[dc][r] = acc;
    }
    __syncthreads();

    for (int idx = tid; idx < 4096; idx += 256) {
        int dr = idx >> 6, rc = idx & 63;
        g_xlt[(size_t)(d0 + dr) * 4096 + r0g + rc] = sout[dr][rc];
    }
}

// Chunked scan with smem-cached operands: 1 block per (b,d).
__global__ void __launch_bounds__(256)
scan_kernel(const float* __restrict__ alog_l, const float* __restrict__ dssm_l) {
    const int d = blockIdx.x & 511;
    const int b = blockIdx.x >> 9;
    const int t = threadIdx.x;
    const int n = t & 15;
    const int c = t >> 4;

    __shared__ float sdelta[1024], su[1024], sres[1024];
    __shared__ float sh_hend[16][16];
    __shared__ float sh_S[16];
    __shared__ float sh_y[1024];

    const float Adn = -__expf(alog_l[d * 16 + n]);
    const float Dd = dssm_l[d];

    const size_t base = (size_t)d * 4096 + (size_t)b * 1024;
    *(float4*)&sdelta[t * 4] = *(const float4*)&g_deltat[base + t * 4];
    *(float4*)&su[t * 4]     = *(const float4*)&g_xlt[base + t * 4];
    *(float4*)&sres[t * 4]   = *(const float4*)&g_rest[base + t * 4];

    const int rb = b * 1024 + c * 64;
    const float* pB = g_xdbl + ((size_t)rb << 6) + 32 + n;
    const float* pC = g_xdbl + ((size_t)rb << 6) + 48 + n;
    __syncthreads();

    float h = 0.f, S = 0.f;
#pragma unroll 4
    for (int j = 0; j < 64; j++) {
        float dl = sdelta[c * 64 + j];
        float u  = su[c * 64 + j];
        float Bv = pB[j << 6];
        float a = __expf(dl * Adn);
        h = fmaf(a, h, dl * Bv * u);
        S += dl;
    }
    sh_hend[c][n] = h;
    if (n == 0) sh_S[c] = S;
    __syncthreads();

    float H0 = 0.f, Q = 0.f;
    for (int cp = c - 1; cp >= 0; cp--) {
        H0 = fmaf(sh_hend[cp][n], __expf(Adn * Q), H0);
        Q += sh_S[cp];
    }

    h = H0;
#pragma unroll 2
    for (int j = 0; j < 64; j++) {
        float dl = sdelta[c * 64 + j];
        float u  = su[c * 64 + j];
        float Bv = pB[j << 6];
        float Cv = pC[j << 6];
        float a = __expf(dl * Adn);
        h = fmaf(a, h, dl * Bv * u);
        float p = h * Cv;
        p += __shfl_xor_sync(0xFFFFFFFFu, p, 1);
        p += __shfl_xor_sync(0xFFFFFFFFu, p, 2);
        p += __shfl_xor_sync(0xFFFFFFFFu, p, 4);
        p += __shfl_xor_sync(0xFFFFFFFFu, p, 8);
        if (n == 0) {
            float sr = sres[c * 64 + j];
            sh_y[c * 64 + j] = tf32r((p + u * Dd) * sr);
        }
    }
    __syncthreads();

    *(float4*)&g_yt[base + t * 4] = *(float4*)&sh_y[t * 4];
}

// LN + residual add, warp-shuffle reductions; maintains rounded mirror g_sr
__global__ void ln_add_kernel(const float* __restrict__ w, const float* __restrict__ bi) {
    const int row = blockIdx.x;
    const int t = threadIdx.x;
    const int lane = t & 31, warp = t >> 5;
    __shared__ float shm[8], shv[8];
    float v = g_tmp[(size_t)row * 256 + t];

    float s = v;
#pragma unroll
    for (int o = 16; o > 0; o >>= 1) s += __shfl_xor_sync(0xFFFFFFFFu, s, o);
    if (lane == 0) shm[warp] = s;
    __syncthreads();
    float tot = shm[0] + shm[1] + shm[2] + shm[3] + shm[4] + shm[5] + shm[6] + shm[7];
    float mean = tot * (1.f / 256.f);

    float dv = v - mean;
    float q = dv * dv;
#pragma unroll
    for (int o = 16; o > 0; o >>= 1) q += __shfl_xor_sync(0xFFFFFFFFu, q, o);
    if (lane == 0) shv[warp] = q;
    __syncthreads();
    float vtot = shv[0] + shv[1] + shv[2] + shv[3] + shv[4] + shv[5] + shv[6] + shv[7];
    float var = vtot * (1.f / 256.f);

    float ns = g_s[(size_t)row * 256 + t] + dv * rsqrtf(var + EPSV) * w[t] + bi[t];
    g_s[(size_t)row * 256 + t] = ns;
    g_sr[(size_t)row * 256 + t] = tf32r(ns);
}

// ---------------- head ----------------
__global__ void head1_kernel() {
    int b = blockIdx.x >> 5, ch = blockIdx.x & 31, t = threadIdx.x;
    float acc = 0.f;
    const float* p = g_s + (size_t)((b << 10) + ch * 32) * 256 + t;
#pragma unroll 8
    for (int l = 0; l < 32; l++) acc += p[(size_t)l * 256];
    g_part[blockIdx.x * 256 + t] = acc;
}

__global__ void head2_kernel(const float* __restrict__ nw, const float* __restrict__ nb) {
    int b = blockIdx.x, t = threadIdx.x;
    float acc = 0.f;
#pragma unroll
    for (int c = 0; c < 32; c++) acc += g_part[((b << 5) + c) * 256 + t];
    float m = acc * (1.f / 1024.f);
    __shared__ float sh[256];
    sh[t] = m;
    __syncthreads();
    for (int o = 128; o > 0; o >>= 1) { if (t < o) sh[t] += sh[t + o]; __syncthreads(); }
    float mu = sh[0] * (1.f / 256.f);
    __syncthreads();
    float dv = m - mu;
    sh[t] = dv * dv;
    __syncthreads();
    for (int o = 128; o > 0; o >>= 1) { if (t < o) sh[t] += sh[t + o]; __syncthreads(); }
    float var = sh[0] * (1.f / 256.f);
    g_v[b * 256 + t] = dv * rsqrtf(var + EPSV) * nw[t] + nb[t];
}

__global__ void fc_kernel(const float* __restrict__ fcw, const float* __restrict__ fcb,
                          float* __restrict__ out) {
    int idx = blockIdx.x * 256 + threadIdx.x;
    if (idx >= 4000) return;
    int b = idx / 1000, n = idx % 1000;
    float acc = fcb[n];
    const float* v = g_v + b * 256;
    const float* w = fcw + n * 256;
#pragma unroll 8
    for (int k = 0; k < 256; k++) acc += v[k] * w[k];
    out[idx] = acc;
}

__global__ void softmax_kernel(float* __restrict__ out) {
    int b = blockIdx.x, t = threadIdx.x;
    __shared__ float sh[256];
    const float* lg = out + b * 1000;
    float mx = -1e30f;
    for (int i = t; i < 1000; i += 256) mx = fmaxf(mx, lg[i]);
    sh[t] = mx;
    __syncthreads();
    for (int o = 128; o > 0; o >>= 1) { if (t < o) sh[t] = fmaxf(sh[t], sh[t + o]); __syncthreads(); }
    mx = sh[0];
    __syncthreads();
    float s = 0.f;
    for (int i = t; i < 1000; i += 256) s += expf(lg[i] - mx);
    sh[t] = s;
    __syncthreads();
    for (int o = 128; o > 0; o >>= 1) { if (t < o) sh[t] += sh[t + o]; __syncthreads(); }
    float inv = 1.f / sh[0];
    for (int i = t; i < 1000; i += 256) out[4000 + b * 1000 + i] = expf(lg[i] - mx) * inv;
}

// ---------------- launch ----------------
extern "C" void kernel_launch(void* const* d_in, const int* in_sizes, int n_in,
                              void* d_out, int out_size) {
    const float* x    = (const float*)d_in[0];
    const float* c1w  = (const float*)d_in[1];
    const float* c1b  = (const float*)d_in[2];
    const float* g1   = (const float*)d_in[3];
    const float* b1   = (const float*)d_in[4];
    const float* c2w  = (const float*)d_in[5];
    const float* c2b  = (const float*)d_in[6];
    const float* g2   = (const float*)d_in[7];
    const float* b2   = (const float*)d_in[8];
    const float* pw   = (const float*)d_in[9];
    const float* pb   = (const float*)d_in[10];
    const float* g3   = (const float*)d_in[11];
    const float* b3   = (const float*)d_in[12];
    const float* ipw  = (const float*)d_in[13];
    const float* ipb  = (const float*)d_in[14];
    const float* cw   = (const float*)d_in[15];
    const float* cb   = (const float*)d_in[16];
    const float* xpw  = (const float*)d_in[17];
    const float* dpw  = (const float*)d_in[18];
    const float* dpb  = (const float*)d_in[19];
    const float* alog = (const float*)d_in[20];
    const float* dssm = (const float*)d_in[21];
    const float* opw  = (const float*)d_in[22];
    const float* opb  = (const float*)d_in[23];
    const float* lnw  = (const float*)d_in[24];
    const float* lnb  = (const float*)d_in[25];
    const float* nw   = (const float*)d_in[26];
    const float* nb   = (const float*)d_in[27];
    const float* fcw  = (const float*)d_in[28];
    const float* fcb  = (const float*)d_in[29];

    float *p_s, *p_sr, *p_xr, *p_xlt, *p_xdbl, *p_deltat, *p_rest, *p_yt, *p_tmp;
    float *p_h2, *p_w2p, *p_wpp, *p_ipwr, *p_opwr;
    cudaGetSymbolAddress((void**)&p_s, g_s);
    cudaGetSymbolAddress((void**)&p_sr, g_sr);
    cudaGetSymbolAddress((void**)&p_xr, g_xr);
    cudaGetSymbolAddress((void**)&p_xlt, g_xlt);
    cudaGetSymbolAddress((void**)&p_xdbl, g_xdbl);
    cudaGetSymbolAddress((void**)&p_deltat, g_deltat);
    cudaGetSymbolAddress((void**)&p_rest, g_rest);
    cudaGetSymbolAddress((void**)&p_yt, g_yt);
    cudaGetSymbolAddress((void**)&p_tmp, g_tmp);
    cudaGetSymbolAddress((void**)&p_h2, g_h2);
    cudaGetSymbolAddress((void**)&p_w2p, g_w2p);
    cudaGetSymbolAddress((void**)&p_wpp, g_wpp);
    cudaGetSymbolAddress((void**)&p_ipwr, g_ipwr);
    cudaGetSymbolAddress((void**)&p_opwr, g_opwr);

    constexpr int SM128 = 2 * 128 * 144 + 2 * 128 * 144;       // 73728
    constexpr int SM64 = 2 * 64 * 144 + 2 * 128 * 144;         // 55296
    constexpr int SMTN64 = 2 * (32 * 72 * 4) + 2 * 18432;      // 55296
    cudaFuncSetAttribute(mm_gemm<128, 1, 2, 0, 1, 0>, cudaFuncAttributeMaxDynamicSharedMemorySize, SM128);
    cudaFuncSetAttribute(mm_gemm<64, 2, 2, 0, 0, 1>, cudaFuncAttributeMaxDynamicSharedMemorySize, SM64);
    cudaFuncSetAttribute(mm_gemm<128, 0, 4, 0, 0, 2>, cudaFuncAttributeMaxDynamicSharedMemorySize, SM128);
    cudaFuncSetAttribute(mm_gemm_tn<64, 1>, cudaFuncAttributeMaxDynamicSharedMemorySize, SMTN64);

    // ---- one-time weight prep (fused into a single launch) ----
    const int PREP_N = 256 * 1152 + 256 * 1024 + 4 * 1024 * 256 + 4 * 256 * 512;
    prep_kernel<<<(PREP_N + 255) / 256, 256>>>(c2w, pw, ipw, opw);

    // ---- stem ----
    conv1_kernel<<<8192, 256>>>(x, c1w, c1b, g1, b1);
    mm_gemm<128, 1, 2, 0, 1, 0><<<dim3(2, 128), 256, SM128>>>(
        nullptr, 0, p_w2p, 1152, p_h2, 256, 1152, c2b, g2, b2, nullptr, 0);
    // patchify: writes fp32 g_s + rounded mirror g_sr
    mm_gemm<64, 2, 2, 0, 0, 1><<<dim3(2, 64), 256, SM64>>>(
        nullptr, 0, p_wpp, 1024, p_s, 256, 1024, pb, g3, b3, p_sr, 0);

    // ---- mamba layers ----
    for (int i = 0; i < 4; i++) {
        const float* ipw_l  = p_ipwr + (size_t)i * 1024 * 256;
        const float* ipb_l  = ipb + (size_t)i * 1024;
        const float* cw_l   = cw + (size_t)i * 512 * 4;
        const float* cb_l   = cb + (size_t)i * 512;
        const float* xpw_l  = xpw + (size_t)i * 64 * 512;
        const float* dpw_l  = dpw + (size_t)i * 512 * 32;
        const float* dpb_l  = dpb + (size_t)i * 512;
        const float* alog_l = alog + (size_t)i * 512 * 16;
        const float* dssm_l = dssm + (size_t)i * 512;
        const float* opw_l  = p_opwr + (size_t)i * 256 * 512;
        const float* opb_l  = opb + (size_t)i * 256;
        const float* lnw_l  = lnw + (size_t)i * 256;
        const float* lnb_l  = lnb + (size_t)i * 256;

        // in_proj (tf32 mma, A pre-rounded g_sr): xi -> g_xr, silu(res) -> g_rest^T
        mm_gemm<128, 0, 4, 0, 0, 2><<<dim3(8, 32), 256, SM128>>>(
            p_sr, 256, ipw_l, 256, p_xr, 1024, 256, ipb_l, nullptr, nullptr,
            p_rest, 4096);
        dwconv_t_kernel<<<dim3(64, 8), 256>>>(cw_l, cb_l);
        // x_proj (TN FFMA, 32-row tiles)
        sgemm_tn32<<<dim3(1, 128), 128>>>(p_xlt, 4096, xpw_l, 512, p_xdbl, 64, 512);
        // dt_proj TRANSPOSED (FFMA): M=512(d), N=4096(rows), K=32
        sgemm_nt<64, 128, 8, 8, 5><<<dim3(32, 8), 128>>>(dpw_l, 32, p_xdbl, 64,
                                                         p_deltat, 4096, 32, dpb_l);
        scan_kernel<<<2048, 256>>>(alog_l, dssm_l);
        // out_proj (TN tf32 mma, A = g_yt K-major)
        mm_gemm_tn<64, 1><<<dim3(2, 64), 256, SMTN64>>>(p_yt, 4096, opw_l, 512,
                                                        p_tmp, 256, 512, opb_l);
        ln_add_kernel<<<4096, 256>>>(lnw_l, lnb_l);
    }

    // ---- head ----
    head1_kernel<<<128, 256>>>();
    head2_kernel<<<4, 256>>>(nw, nb);
    fc_kernel<<<16, 256>>>(fcw, fcb, (float*)d_out);
    if (out_size >= 8000) softmax_kernel<<<4, 256>>>((float*)d_out);
}